// round 1
// baseline (speedup 1.0000x reference)
#include <cuda_runtime.h>

// RBF-kernel causal attention, fp32 SIMT tiled (flash-attention style).
// B=2, H=16, N=2048, D=64.
//
// logits = -relu(||q||^2 + ||k||^2 - 2 q.k) / 8, causal, softmax, @ V.
// Since logits <= 0 and |logits| is bounded (~<100 in practice, need >87*8=700
// dist to underflow fp32 exp), we skip online-max tracking: p = exp(logit),
// l = sum p, O = (P @ V) / l.

#define B_   2
#define H_   16
#define N_   2048
#define D_   64
#define BM   64
#define BN   64
#define LDA  68            // padded smem row stride (floats)
#define NTH  256

#define SMEM_FLOATS (4 * 64 * LDA + 2 * 64)
#define SMEM_BYTES  (SMEM_FLOATS * 4)

__global__ void __launch_bounds__(NTH)
rbf_attn_kernel(const float* __restrict__ Qg, const float* __restrict__ Kg,
                const float* __restrict__ Vg, float* __restrict__ Og)
{
    extern __shared__ float sm[];
    float* sQ  = sm;                 // [D_][LDA]  d-major (transposed)
    float* sK  = sQ + D_ * LDA;      // [D_][LDA]  d-major (transposed)
    float* sV  = sK + D_ * LDA;      // [BN][LDA]  n-major (natural)
    float* sP  = sV + BN * LDA;      // [BM][LDA]
    float* qsq = sP + BM * LDA;      // [BM]
    float* ksq = qsq + BM;           // [BN]

    const int tid = threadIdx.x;
    const int ty  = tid >> 4;        // 0..15 -> queries ty*4..ty*4+3
    const int tx  = tid & 15;        // 0..15 -> keys/dims tx*4..tx*4+3
    const int bh  = blockIdx.y;
    const int qt  = (gridDim.x - 1) - blockIdx.x;   // heavy tiles launch first
    const int m0  = qt * BM;

    const float* Qh = Qg + (size_t)bh * N_ * D_;
    const float* Kh = Kg + (size_t)bh * N_ * D_;
    const float* Vh = Vg + (size_t)bh * N_ * D_;
    float*       Oh = Og + (size_t)bh * N_ * D_;

    // ---- load Q tile (transposed into d-major smem) ----
#pragma unroll
    for (int i = 0; i < 4; i++) {
        int fidx = i * NTH + tid;            // 0..1023 float4 index
        int m    = fidx >> 4;                // 0..63
        int d4   = (fidx & 15) << 2;         // 0..60
        float4 qv = *(const float4*)&Qh[(size_t)(m0 + m) * D_ + d4];
        sQ[(d4 + 0) * LDA + m] = qv.x;
        sQ[(d4 + 1) * LDA + m] = qv.y;
        sQ[(d4 + 2) * LDA + m] = qv.z;
        sQ[(d4 + 3) * LDA + m] = qv.w;
    }
    __syncthreads();
    if (tid < BM) {
        float s = 0.f;
#pragma unroll
        for (int d = 0; d < D_; d++) { float x = sQ[d * LDA + tid]; s += x * x; }
        qsq[tid] = s;
    }
    __syncthreads();

    float o[4][4] = {};
    float l[4]    = {0.f, 0.f, 0.f, 0.f};
    float qsr[4];
#pragma unroll
    for (int qi = 0; qi < 4; qi++) qsr[qi] = qsq[ty * 4 + qi];

    // p = exp(-dist2/8) = exp2(-dist2 * 0.125 * log2(e))
    const float CEXP = 0.18033688011112042f;

    for (int kt = 0; kt <= qt; kt++) {
        const int n0 = kt * BN;
        __syncthreads();   // protect smem reuse from previous iteration

        // ---- load K (transposed) and V (natural) tiles ----
#pragma unroll
        for (int i = 0; i < 4; i++) {
            int fidx = i * NTH + tid;
            int n    = fidx >> 4;
            int d4   = (fidx & 15) << 2;
            float4 kv = *(const float4*)&Kh[(size_t)(n0 + n) * D_ + d4];
            sK[(d4 + 0) * LDA + n] = kv.x;
            sK[(d4 + 1) * LDA + n] = kv.y;
            sK[(d4 + 2) * LDA + n] = kv.z;
            sK[(d4 + 3) * LDA + n] = kv.w;
            float4 vv = *(const float4*)&Vh[(size_t)(n0 + n) * D_ + d4];
            *(float4*)&sV[n * LDA + d4] = vv;
        }
        __syncthreads();
        if (tid < BN) {
            float s = 0.f;
#pragma unroll
            for (int d = 0; d < D_; d++) { float x = sK[d * LDA + tid]; s += x * x; }
            ksq[tid] = s;
        }
        __syncthreads();

        // ---- S = Q . K^T  (4x4 micro-tile per thread) ----
        float s[4][4] = {};
#pragma unroll 8
        for (int d = 0; d < D_; d++) {
            float4 qf = *(const float4*)&sQ[d * LDA + ty * 4];
            float4 kf = *(const float4*)&sK[d * LDA + tx * 4];
            const float qa[4] = {qf.x, qf.y, qf.z, qf.w};
            const float ka[4] = {kf.x, kf.y, kf.z, kf.w};
#pragma unroll
            for (int qi = 0; qi < 4; qi++)
#pragma unroll
                for (int ki = 0; ki < 4; ki++)
                    s[qi][ki] = fmaf(qa[qi], ka[ki], s[qi][ki]);
        }

        float ksr[4];
#pragma unroll
        for (int ki = 0; ki < 4; ki++) ksr[ki] = ksq[tx * 4 + ki];

        // ---- logits -> p, accumulate l, stage P in smem ----
#pragma unroll
        for (int qi = 0; qi < 4; qi++) {
            const int m = m0 + ty * 4 + qi;
            float4 pv;
            float* pp = &pv.x;
#pragma unroll
            for (int ki = 0; ki < 4; ki++) {
                const int n = n0 + tx * 4 + ki;
                float d2 = qsr[qi] + ksr[ki] - 2.f * s[qi][ki];
                d2 = fmaxf(d2, 0.f);
                float p = exp2f(-CEXP * d2);
                p = (n <= m) ? p : 0.f;
                l[qi] += p;
                pp[ki] = p;
            }
            *(float4*)&sP[(ty * 4 + qi) * LDA + tx * 4] = pv;
        }
        __syncthreads();

        // ---- O += P @ V ----
#pragma unroll 4
        for (int n4 = 0; n4 < 16; n4++) {
            float4 pr[4], vr[4];
#pragma unroll
            for (int qi = 0; qi < 4; qi++)
                pr[qi] = *(const float4*)&sP[(ty * 4 + qi) * LDA + n4 * 4];
#pragma unroll
            for (int j = 0; j < 4; j++)
                vr[j] = *(const float4*)&sV[(n4 * 4 + j) * LDA + tx * 4];
#pragma unroll
            for (int qi = 0; qi < 4; qi++) {
                const float pa[4] = {pr[qi].x, pr[qi].y, pr[qi].z, pr[qi].w};
#pragma unroll
                for (int j = 0; j < 4; j++) {
                    o[qi][0] = fmaf(pa[j], vr[j].x, o[qi][0]);
                    o[qi][1] = fmaf(pa[j], vr[j].y, o[qi][1]);
                    o[qi][2] = fmaf(pa[j], vr[j].z, o[qi][2]);
                    o[qi][3] = fmaf(pa[j], vr[j].w, o[qi][3]);
                }
            }
        }
    }

    // ---- reduce l across the 16-lane tx group (lanes [0..15]/[16..31] share ty) ----
#pragma unroll
    for (int qi = 0; qi < 4; qi++) {
        float lv = l[qi];
        lv += __shfl_xor_sync(0xffffffffu, lv, 8, 16);
        lv += __shfl_xor_sync(0xffffffffu, lv, 4, 16);
        lv += __shfl_xor_sync(0xffffffffu, lv, 2, 16);
        lv += __shfl_xor_sync(0xffffffffu, lv, 1, 16);
        l[qi] = lv;
    }

    // ---- normalize and write O ----
#pragma unroll
    for (int qi = 0; qi < 4; qi++) {
        const float inv = 1.0f / l[qi];
        float4 ov = make_float4(o[qi][0] * inv, o[qi][1] * inv,
                                o[qi][2] * inv, o[qi][3] * inv);
        *(float4*)&Oh[(size_t)(m0 + ty * 4 + qi) * D_ + tx * 4] = ov;
    }
}

extern "C" void kernel_launch(void* const* d_in, const int* in_sizes, int n_in,
                              void* d_out, int out_size)
{
    const float* q = (const float*)d_in[0];
    const float* k = (const float*)d_in[1];
    const float* v = (const float*)d_in[2];
    float* o = (float*)d_out;

    (void)in_sizes; (void)n_in; (void)out_size;

    cudaFuncSetAttribute(rbf_attn_kernel,
                         cudaFuncAttributeMaxDynamicSharedMemorySize, SMEM_BYTES);

    dim3 grid(N_ / BM, B_ * H_);
    rbf_attn_kernel<<<grid, NTH, SMEM_BYTES>>>(q, k, v, o);
}

// round 2
// speedup vs baseline: 1.2054x; 1.2054x over previous
#include <cuda_runtime.h>

// RBF-kernel causal attention, fp32 SIMT with packed f32x2 FMA.
// B=2, H=16, N=2048, D=64.  BM=128 queries/CTA, BN=64 keys/tile, 256 threads.
// Thread micro-tile: 8 queries x 4 keys (keys interleaved by 16).
// Smem: Q,K stored d-major (transposed), P stored transposed [key][query].

#define N_   2048
#define D_   64
#define BM   128
#define BN   64
#define NTH  256
#define LDQ  132      // sQ row stride (floats): 33 float4s (odd) -> conflict-free
#define LDK  68       // sK row stride: 17 float4s (odd)
#define LDV  68
#define LDP  132      // sPT row stride

#define SQ_OFF   0
#define SK_OFF   (SQ_OFF + 64*LDQ)
#define SV_OFF   (SK_OFF + 64*LDK)
#define SPT_OFF  (SV_OFF + BN*LDV)
#define QSQ_OFF  (SPT_OFF + BN*LDP)
#define KSQ_OFF  (QSQ_OFF + BM)
#define SMEM_FLOATS (KSQ_OFF + BN)
#define SMEM_BYTES  (SMEM_FLOATS * 4)

typedef unsigned long long ull;

// exp2(-dist2/8): p = ex2(dist2 * -log2(e)/8)
#define CEXP 0.18033688011112042f

__device__ __forceinline__ ull ffma2(ull a, ull b, ull c) {
    ull d;
    asm("fma.rn.f32x2 %0, %1, %2, %3;" : "=l"(d) : "l"(a), "l"(b), "l"(c));
    return d;
}
__device__ __forceinline__ ull pack2(float x) {
    ull d;
    asm("mov.b64 %0, {%1, %1};" : "=l"(d) : "f"(x));
    return d;
}
__device__ __forceinline__ float2 unpack2(ull a) {
    float2 f;
    asm("mov.b64 {%0, %1}, %2;" : "=f"(f.x), "=f"(f.y) : "l"(a));
    return f;
}
__device__ __forceinline__ float ex2(float x) {
    float y;
    asm("ex2.approx.f32 %0, %1;" : "=f"(y) : "f"(x));
    return y;
}

template<bool MASKED>
__device__ __forceinline__ void do_tile(
    float* sm, const float* __restrict__ Kh, const float* __restrict__ Vh,
    int n0, int m0, int tid, int tx, int ty,
    const float* qsr, ull* o2, float* l)
{
    __syncthreads();   // protect sK/sV/sPT from previous iteration's readers

    // ---- load K (transposed, lane-per-d) and V (natural) ----
    {
        const int d  = tid & 63;
        const int g0 = tid >> 6;
        const float* Kb = Kh + (size_t)n0 * D_ + d;
#pragma unroll
        for (int r = 0; r < 4; r++) {
            const int g = g0 + 4 * r;           // key group of 4
            float a = Kb[(4*g + 0) * D_];
            float b = Kb[(4*g + 1) * D_];
            float c = Kb[(4*g + 2) * D_];
            float e = Kb[(4*g + 3) * D_];
            *(float4*)&sm[SK_OFF + d * LDK + 4*g] = make_float4(a, b, c, e);
        }
        const float4* Vb = (const float4*)(Vh + (size_t)n0 * D_);
#pragma unroll
        for (int i = 0; i < 4; i++) {
            const int fidx = i * NTH + tid;     // 0..1023
            const int n  = fidx >> 4;
            const int c4 = (fidx & 15) << 2;
            *(float4*)&sm[SV_OFF + n * LDV + c4] = Vb[fidx];
        }
    }
    __syncthreads();
    if (tid < BN) {
        float s = 0.f;
#pragma unroll
        for (int d = 0; d < D_; d++) {
            float x = sm[SK_OFF + d * LDK + tid];
            s = fmaf(x, x, s);
        }
        sm[KSQ_OFF + tid] = s;
    }
    __syncthreads();

    // ---- S = Q.K^T : 4 query-pairs x 4 interleaved keys, f32x2 ----
    ull s2[4][4];
#pragma unroll
    for (int a = 0; a < 4; a++)
#pragma unroll
        for (int b = 0; b < 4; b++) s2[a][b] = 0ull;

    const float* sQb = &sm[SQ_OFF + ty * 8];
    const float* sKb = &sm[SK_OFF + tx];
#pragma unroll 8
    for (int d = 0; d < D_; d++) {
        float4 qa = *(const float4*)&sQb[d * LDQ];
        float4 qb = *(const float4*)&sQb[d * LDQ + 4];
        ull q01 = ((const ull*)&qa)[0];
        ull q23 = ((const ull*)&qa)[1];
        ull q45 = ((const ull*)&qb)[0];
        ull q67 = ((const ull*)&qb)[1];
#pragma unroll
        for (int i = 0; i < 4; i++) {
            ull kk = pack2(sKb[d * LDK + 16 * i]);
            s2[0][i] = ffma2(q01, kk, s2[0][i]);
            s2[1][i] = ffma2(q23, kk, s2[1][i]);
            s2[2][i] = ffma2(q45, kk, s2[2][i]);
            s2[3][i] = ffma2(q67, kk, s2[3][i]);
        }
    }

    // ---- logits -> p -> sPT (transposed: [key][query]) ----
    float* sPTb = &sm[SPT_OFF];
#pragma unroll
    for (int i = 0; i < 4; i++) {
        const int key = tx + 16 * i;
        const float ks = sm[KSQ_OFF + key];
        const int n = n0 + key;
        float p[8];
#pragma unroll
        for (int pi = 0; pi < 4; pi++) {
            float2 s = unpack2(s2[pi][i]);
            float d2a = fmaxf(qsr[2*pi]   + ks - 2.f * s.x, 0.f);
            float d2b = fmaxf(qsr[2*pi+1] + ks - 2.f * s.y, 0.f);
            float pa = ex2(d2a * -CEXP);
            float pb = ex2(d2b * -CEXP);
            if (MASKED) {
                if (n > m0 + ty * 8 + 2*pi)     pa = 0.f;
                if (n > m0 + ty * 8 + 2*pi + 1) pb = 0.f;
            }
            l[2*pi]     += pa;
            l[2*pi + 1] += pb;
            p[2*pi] = pa; p[2*pi+1] = pb;
        }
        *(float4*)&sPTb[key * LDP + ty * 8]     = make_float4(p[0], p[1], p[2], p[3]);
        *(float4*)&sPTb[key * LDP + ty * 8 + 4] = make_float4(p[4], p[5], p[6], p[7]);
    }
    __syncthreads();

    // ---- O += P @ V : query-pairs packed, v broadcast-packed ----
    const float* sVb = &sm[SV_OFF + tx * 4];
#pragma unroll 2
    for (int j0 = 0; j0 < BN; j0 += 4) {
#pragma unroll
        for (int j = 0; j < 4; j++) {
            const int key = j0 + j;
            float4 pA = *(const float4*)&sPTb[key * LDP + ty * 8];
            float4 pB = *(const float4*)&sPTb[key * LDP + ty * 8 + 4];
            float4 vv = *(const float4*)&sVb[key * LDV];
            ull p01 = ((const ull*)&pA)[0];
            ull p23 = ((const ull*)&pA)[1];
            ull p45 = ((const ull*)&pB)[0];
            ull p67 = ((const ull*)&pB)[1];
            const float* vf = (const float*)&vv;
#pragma unroll
            for (int dc = 0; dc < 4; dc++) {
                ull vd = pack2(vf[dc]);
                o2[0*4 + dc] = ffma2(p01, vd, o2[0*4 + dc]);
                o2[1*4 + dc] = ffma2(p23, vd, o2[1*4 + dc]);
                o2[2*4 + dc] = ffma2(p45, vd, o2[2*4 + dc]);
                o2[3*4 + dc] = ffma2(p67, vd, o2[3*4 + dc]);
            }
        }
    }
}

__global__ void __launch_bounds__(NTH, 2)
rbf_attn_kernel(const float* __restrict__ Qg, const float* __restrict__ Kg,
                const float* __restrict__ Vg, float* __restrict__ Og)
{
    extern __shared__ float sm[];
    const int tid = threadIdx.x;
    const int tx  = tid & 15;
    const int ty  = tid >> 4;
    const int bh  = blockIdx.y;
    const int qt  = (gridDim.x - 1) - blockIdx.x;   // heavy tiles first
    const int m0  = qt * BM;

    const float* Qh = Qg + (size_t)bh * N_ * D_;
    const float* Kh = Kg + (size_t)bh * N_ * D_;
    const float* Vh = Vg + (size_t)bh * N_ * D_;
    float*       Oh = Og + (size_t)bh * N_ * D_;

    // ---- load Q (transposed, lane-per-d, conflict-free STS.128) ----
    {
        const int d  = tid & 63;
        const int mg = tid >> 6;
        const float* Qb = Qh + (size_t)m0 * D_ + d;
#pragma unroll
        for (int r = 0; r < 8; r++) {
            const int g = mg + 4 * r;            // query group of 4
            float a = Qb[(4*g + 0) * D_];
            float b = Qb[(4*g + 1) * D_];
            float c = Qb[(4*g + 2) * D_];
            float e = Qb[(4*g + 3) * D_];
            *(float4*)&sm[SQ_OFF + d * LDQ + 4*g] = make_float4(a, b, c, e);
        }
    }
    __syncthreads();
    if (tid < BM) {
        float s = 0.f;
#pragma unroll
        for (int d = 0; d < D_; d++) {
            float x = sm[SQ_OFF + d * LDQ + tid];
            s = fmaf(x, x, s);
        }
        sm[QSQ_OFF + tid] = s;
    }
    __syncthreads();

    float qsr[8];
#pragma unroll
    for (int q = 0; q < 8; q++) qsr[q] = sm[QSQ_OFF + ty * 8 + q];

    ull o2[16];
#pragma unroll
    for (int i = 0; i < 16; i++) o2[i] = 0ull;
    float l[8] = {0.f, 0.f, 0.f, 0.f, 0.f, 0.f, 0.f, 0.f};

    int kt = 0;
    for (; kt < 2 * qt; kt++)
        do_tile<false>(sm, Kh, Vh, kt * BN, m0, tid, tx, ty, qsr, o2, l);
    for (; kt < 2 * qt + 2; kt++)
        do_tile<true>(sm, Kh, Vh, kt * BN, m0, tid, tx, ty, qsr, o2, l);

    // ---- reduce l across the 16 tx lanes sharing this query group ----
#pragma unroll
    for (int q = 0; q < 8; q++) {
        float lv = l[q];
        lv += __shfl_xor_sync(0xffffffffu, lv, 8, 16);
        lv += __shfl_xor_sync(0xffffffffu, lv, 4, 16);
        lv += __shfl_xor_sync(0xffffffffu, lv, 2, 16);
        lv += __shfl_xor_sync(0xffffffffu, lv, 1, 16);
        l[q] = lv;
    }

    // ---- normalize and write O ----
#pragma unroll
    for (int pi = 0; pi < 4; pi++) {
        float2 od[4];
#pragma unroll
        for (int dc = 0; dc < 4; dc++) od[dc] = unpack2(o2[pi * 4 + dc]);
        const int mA = m0 + ty * 8 + 2 * pi;
        const float invA = 1.0f / l[2*pi];
        const float invB = 1.0f / l[2*pi + 1];
        float4 outA = make_float4(od[0].x * invA, od[1].x * invA,
                                  od[2].x * invA, od[3].x * invA);
        float4 outB = make_float4(od[0].y * invB, od[1].y * invB,
                                  od[2].y * invB, od[3].y * invB);
        *(float4*)&Oh[(size_t)mA       * D_ + tx * 4] = outA;
        *(float4*)&Oh[(size_t)(mA + 1) * D_ + tx * 4] = outB;
    }
}

extern "C" void kernel_launch(void* const* d_in, const int* in_sizes, int n_in,
                              void* d_out, int out_size)
{
    const float* q = (const float*)d_in[0];
    const float* k = (const float*)d_in[1];
    const float* v = (const float*)d_in[2];
    float* o = (float*)d_out;
    (void)in_sizes; (void)n_in; (void)out_size;

    cudaFuncSetAttribute(rbf_attn_kernel,
                         cudaFuncAttributeMaxDynamicSharedMemorySize, SMEM_BYTES);

    dim3 grid(N_ / BM, 32);
    rbf_attn_kernel<<<grid, NTH, SMEM_BYTES>>>(q, k, v, o);
}

// round 3
// speedup vs baseline: 1.2293x; 1.0199x over previous
#include <cuda_runtime.h>

// RBF-kernel causal attention, fp32 SIMT with packed f32x2 FMA.
// B=2, H=16, N=2048, D=64.  BM=128 queries/CTA, BN=64 keys/tile, 256 threads.
// Thread micro-tile: 8 queries x 4 keys (keys interleaved by 16).
// Smem: Q,K stored d-major (transposed), P stored transposed [key][query].

#define N_   2048
#define D_   64
#define BM   128
#define BN   64
#define NTH  256
#define LDQ  132      // sQ row stride (floats): 33 float4s (odd) -> conflict-free
#define LDK  68       // sK row stride: 17 float4s (odd)
#define LDV  68
#define LDP  132      // sPT row stride

#define SQ_OFF   0
#define SK_OFF   (SQ_OFF + 64*LDQ)
#define SV_OFF   (SK_OFF + 64*LDK)
#define SPT_OFF  (SV_OFF + BN*LDV)
#define QSQ_OFF  (SPT_OFF + BN*LDP)
#define KSQ_OFF  (QSQ_OFF + BM)
#define SMEM_FLOATS (KSQ_OFF + BN)
#define SMEM_BYTES  (SMEM_FLOATS * 4)

typedef unsigned long long ull;

// exp2(-dist2/8): p = ex2(dist2 * -log2(e)/8)
#define CEXP 0.18033688011112042f

__device__ __forceinline__ ull ffma2(ull a, ull b, ull c) {
    ull d;
    asm("fma.rn.f32x2 %0, %1, %2, %3;" : "=l"(d) : "l"(a), "l"(b), "l"(c));
    return d;
}
__device__ __forceinline__ ull pack2(float x) {
    ull d;
    asm("mov.b64 %0, {%1, %1};" : "=l"(d) : "f"(x));
    return d;
}
__device__ __forceinline__ float2 unpack2(ull a) {
    float2 f;
    asm("mov.b64 {%0, %1}, %2;" : "=f"(f.x), "=f"(f.y) : "l"(a));
    return f;
}
__device__ __forceinline__ float ex2(float x) {
    float y;
    asm("ex2.approx.f32 %0, %1;" : "=f"(y) : "f"(x));
    return y;
}

template<bool MASKED>
__device__ __forceinline__ void do_tile(
    float* sm, const float* __restrict__ Kh, const float* __restrict__ Vh,
    int n0, int m0, int tid, int tx, int ty,
    const float* qsr, ull* o2, float* l)
{
    __syncthreads();   // protect sK/sV/sPT from previous iteration's readers

    // ---- load K (transposed, lane-per-d) and V (natural) ----
    {
        const int d  = tid & 63;
        const int g0 = tid >> 6;
        const float* Kb = Kh + (size_t)n0 * D_ + d;
#pragma unroll
        for (int r = 0; r < 4; r++) {
            const int g = g0 + 4 * r;           // key group of 4
            float a = Kb[(4*g + 0) * D_];
            float b = Kb[(4*g + 1) * D_];
            float c = Kb[(4*g + 2) * D_];
            float e = Kb[(4*g + 3) * D_];
            *(float4*)&sm[SK_OFF + d * LDK + 4*g] = make_float4(a, b, c, e);
        }
        const float4* Vb = (const float4*)(Vh + (size_t)n0 * D_);
#pragma unroll
        for (int i = 0; i < 4; i++) {
            const int fidx = i * NTH + tid;     // 0..1023
            const int n  = fidx >> 4;
            const int c4 = (fidx & 15) << 2;
            *(float4*)&sm[SV_OFF + n * LDV + c4] = Vb[fidx];
        }
    }
    __syncthreads();
    if (tid < BN) {
        float s = 0.f;
#pragma unroll
        for (int d = 0; d < D_; d++) {
            float x = sm[SK_OFF + d * LDK + tid];
            s = fmaf(x, x, s);
        }
        sm[KSQ_OFF + tid] = s;
    }
    __syncthreads();

    // ---- S = Q.K^T : 4 query-pairs x 4 interleaved keys, f32x2 ----
    ull s2[4][4];
#pragma unroll
    for (int a = 0; a < 4; a++)
#pragma unroll
        for (int b = 0; b < 4; b++) s2[a][b] = 0ull;

    const float* sQb = &sm[SQ_OFF + ty * 8];
    const float* sKb = &sm[SK_OFF + tx];
#pragma unroll 8
    for (int d = 0; d < D_; d++) {
        float4 qa = *(const float4*)&sQb[d * LDQ];
        float4 qb = *(const float4*)&sQb[d * LDQ + 4];
        ull q01 = ((const ull*)&qa)[0];
        ull q23 = ((const ull*)&qa)[1];
        ull q45 = ((const ull*)&qb)[0];
        ull q67 = ((const ull*)&qb)[1];
#pragma unroll
        for (int i = 0; i < 4; i++) {
            ull kk = pack2(sKb[d * LDK + 16 * i]);
            s2[0][i] = ffma2(q01, kk, s2[0][i]);
            s2[1][i] = ffma2(q23, kk, s2[1][i]);
            s2[2][i] = ffma2(q45, kk, s2[2][i]);
            s2[3][i] = ffma2(q67, kk, s2[3][i]);
        }
    }

    // ---- logits -> p -> sPT (transposed: [key][query]) ----
    float* sPTb = &sm[SPT_OFF];
#pragma unroll
    for (int i = 0; i < 4; i++) {
        const int key = tx + 16 * i;
        const float ks = sm[KSQ_OFF + key];
        const int n = n0 + key;
        float p[8];
#pragma unroll
        for (int pi = 0; pi < 4; pi++) {
            float2 s = unpack2(s2[pi][i]);
            float d2a = fmaxf(qsr[2*pi]   + ks - 2.f * s.x, 0.f);
            float d2b = fmaxf(qsr[2*pi+1] + ks - 2.f * s.y, 0.f);
            float pa = ex2(d2a * -CEXP);
            float pb = ex2(d2b * -CEXP);
            if (MASKED) {
                if (n > m0 + ty * 8 + 2*pi)     pa = 0.f;
                if (n > m0 + ty * 8 + 2*pi + 1) pb = 0.f;
            }
            l[2*pi]     += pa;
            l[2*pi + 1] += pb;
            p[2*pi] = pa; p[2*pi+1] = pb;
        }
        *(float4*)&sPTb[key * LDP + ty * 8]     = make_float4(p[0], p[1], p[2], p[3]);
        *(float4*)&sPTb[key * LDP + ty * 8 + 4] = make_float4(p[4], p[5], p[6], p[7]);
    }
    __syncthreads();

    // ---- O += P @ V : query-pairs packed, v broadcast-packed ----
    const float* sVb = &sm[SV_OFF + tx * 4];
#pragma unroll 2
    for (int j0 = 0; j0 < BN; j0 += 4) {
#pragma unroll
        for (int j = 0; j < 4; j++) {
            const int key = j0 + j;
            float4 pA = *(const float4*)&sPTb[key * LDP + ty * 8];
            float4 pB = *(const float4*)&sPTb[key * LDP + ty * 8 + 4];
            float4 vv = *(const float4*)&sVb[key * LDV];
            ull p01 = ((const ull*)&pA)[0];
            ull p23 = ((const ull*)&pA)[1];
            ull p45 = ((const ull*)&pB)[0];
            ull p67 = ((const ull*)&pB)[1];
            const float* vf = (const float*)&vv;
#pragma unroll
            for (int dc = 0; dc < 4; dc++) {
                ull vd = pack2(vf[dc]);
                o2[0*4 + dc] = ffma2(p01, vd, o2[0*4 + dc]);
                o2[1*4 + dc] = ffma2(p23, vd, o2[1*4 + dc]);
                o2[2*4 + dc] = ffma2(p45, vd, o2[2*4 + dc]);
                o2[3*4 + dc] = ffma2(p67, vd, o2[3*4 + dc]);
            }
        }
    }
}

__global__ void __launch_bounds__(NTH, 2)
rbf_attn_kernel(const float* __restrict__ Qg, const float* __restrict__ Kg,
                const float* __restrict__ Vg, float* __restrict__ Og)
{
    extern __shared__ float sm[];
    const int tid = threadIdx.x;
    const int tx  = tid & 15;
    const int ty  = tid >> 4;
    const int bh  = blockIdx.y;
    const int qt  = (gridDim.x - 1) - blockIdx.x;   // heavy tiles first
    const int m0  = qt * BM;

    const float* Qh = Qg + (size_t)bh * N_ * D_;
    const float* Kh = Kg + (size_t)bh * N_ * D_;
    const float* Vh = Vg + (size_t)bh * N_ * D_;
    float*       Oh = Og + (size_t)bh * N_ * D_;

    // ---- load Q (transposed, lane-per-d, conflict-free STS.128) ----
    {
        const int d  = tid & 63;
        const int mg = tid >> 6;
        const float* Qb = Qh + (size_t)m0 * D_ + d;
#pragma unroll
        for (int r = 0; r < 8; r++) {
            const int g = mg + 4 * r;            // query group of 4
            float a = Qb[(4*g + 0) * D_];
            float b = Qb[(4*g + 1) * D_];
            float c = Qb[(4*g + 2) * D_];
            float e = Qb[(4*g + 3) * D_];
            *(float4*)&sm[SQ_OFF + d * LDQ + 4*g] = make_float4(a, b, c, e);
        }
    }
    __syncthreads();
    if (tid < BM) {
        float s = 0.f;
#pragma unroll
        for (int d = 0; d < D_; d++) {
            float x = sm[SQ_OFF + d * LDQ + tid];
            s = fmaf(x, x, s);
        }
        sm[QSQ_OFF + tid] = s;
    }
    __syncthreads();

    float qsr[8];
#pragma unroll
    for (int q = 0; q < 8; q++) qsr[q] = sm[QSQ_OFF + ty * 8 + q];

    ull o2[16];
#pragma unroll
    for (int i = 0; i < 16; i++) o2[i] = 0ull;
    float l[8] = {0.f, 0.f, 0.f, 0.f, 0.f, 0.f, 0.f, 0.f};

    int kt = 0;
    for (; kt < 2 * qt; kt++)
        do_tile<false>(sm, Kh, Vh, kt * BN, m0, tid, tx, ty, qsr, o2, l);
    for (; kt < 2 * qt + 2; kt++)
        do_tile<true>(sm, Kh, Vh, kt * BN, m0, tid, tx, ty, qsr, o2, l);

    // ---- reduce l across the 16 tx lanes sharing this query group ----
#pragma unroll
    for (int q = 0; q < 8; q++) {
        float lv = l[q];
        lv += __shfl_xor_sync(0xffffffffu, lv, 8, 16);
        lv += __shfl_xor_sync(0xffffffffu, lv, 4, 16);
        lv += __shfl_xor_sync(0xffffffffu, lv, 2, 16);
        lv += __shfl_xor_sync(0xffffffffu, lv, 1, 16);
        l[q] = lv;
    }

    // ---- normalize and write O ----
#pragma unroll
    for (int pi = 0; pi < 4; pi++) {
        float2 od[4];
#pragma unroll
        for (int dc = 0; dc < 4; dc++) od[dc] = unpack2(o2[pi * 4 + dc]);
        const int mA = m0 + ty * 8 + 2 * pi;
        const float invA = 1.0f / l[2*pi];
        const float invB = 1.0f / l[2*pi + 1];
        float4 outA = make_float4(od[0].x * invA, od[1].x * invA,
                                  od[2].x * invA, od[3].x * invA);
        float4 outB = make_float4(od[0].y * invB, od[1].y * invB,
                                  od[2].y * invB, od[3].y * invB);
        *(float4*)&Oh[(size_t)mA       * D_ + tx * 4] = outA;
        *(float4*)&Oh[(size_t)(mA + 1) * D_ + tx * 4] = outB;
    }
}

extern "C" void kernel_launch(void* const* d_in, const int* in_sizes, int n_in,
                              void* d_out, int out_size)
{
    const float* q = (const float*)d_in[0];
    const float* k = (const float*)d_in[1];
    const float* v = (const float*)d_in[2];
    float* o = (float*)d_out;
    (void)in_sizes; (void)n_in; (void)out_size;

    cudaFuncSetAttribute(rbf_attn_kernel,
                         cudaFuncAttributeMaxDynamicSharedMemorySize, SMEM_BYTES);

    dim3 grid(N_ / BM, 32);
    rbf_attn_kernel<<<grid, NTH, SMEM_BYTES>>>(q, k, v, o);
}

// round 5
// speedup vs baseline: 2.1222x; 1.7263x over previous
#include <cuda_runtime.h>
#include <cuda_bf16.h>
#include <cstdint>

// RBF-kernel causal attention via warp-level mma.sync (bf16, hi/lo compensated).
// Baseline sm_103 target: no tcgen05 (harness compiles PTX for sm_103, not 103a),
// so use ldmatrix + mma.sync.m16n8k16 (sm_80+ baseline, runs on tensor pipe).
// B=2, H=16, N=2048, D=64. CTA: 64 queries, 4 warps (16 rows each), 64-key tiles.
// QK^T: 3 passes (qh*kh + qh*kl + ql*kh). PV: 3 passes (ph*vh + ph*vl + pl*vh).
// P never leaves registers (C-frag -> A-frag reinterpretation).

#define N_   2048
#define D_   64
#define BM   64
#define BN   64
#define NTH  128
#define LDH  72                      // halves per smem row (144 B: +16B skew)
#define CEXP 0.18033688011112042f    // log2(e)/8

// smem byte offsets
#define OFF_KH  0
#define OFF_KL  (64 * LDH * 2)       //  9216
#define OFF_VH  (2 * 64 * LDH * 2)   // 18432
#define OFF_VL  (3 * 64 * LDH * 2)   // 27648
#define OFF_KSQ (4 * 64 * LDH * 2)   // 36864
#define OFF_QSQ (OFF_KSQ + 256)
#define SMEM_BYTES (OFF_QSQ + 256)

typedef uint32_t u32;

__device__ __forceinline__ u32 smem_u32(const void* p) {
    u32 a;
    asm("{ .reg .u64 t; cvta.to.shared.u64 t, %1; cvt.u32.u64 %0, t; }"
        : "=r"(a) : "l"(p));
    return a;
}
__device__ __forceinline__ float ex2(float x) {
    float y; asm("ex2.approx.f32 %0, %1;" : "=f"(y) : "f"(x)); return y;
}
__device__ __forceinline__ void ldsm4(u32 addr, u32 r[4]) {
    asm volatile("ldmatrix.sync.aligned.m8n8.x4.shared.b16 {%0,%1,%2,%3}, [%4];"
                 : "=r"(r[0]), "=r"(r[1]), "=r"(r[2]), "=r"(r[3]) : "r"(addr));
}
__device__ __forceinline__ void ldsm4t(u32 addr, u32 r[4]) {
    asm volatile("ldmatrix.sync.aligned.m8n8.x4.trans.shared.b16 {%0,%1,%2,%3}, [%4];"
                 : "=r"(r[0]), "=r"(r[1]), "=r"(r[2]), "=r"(r[3]) : "r"(addr));
}
__device__ __forceinline__ void mma16816(float d[4], const u32 a[4], u32 b0, u32 b1) {
    asm volatile(
        "mma.sync.aligned.m16n8k16.row.col.f32.bf16.bf16.f32 "
        "{%0,%1,%2,%3}, {%4,%5,%6,%7}, {%8,%9}, {%0,%1,%2,%3};"
        : "+f"(d[0]), "+f"(d[1]), "+f"(d[2]), "+f"(d[3])
        : "r"(a[0]), "r"(a[1]), "r"(a[2]), "r"(a[3]), "r"(b0), "r"(b1));
}
__device__ __forceinline__ u32 bits2(__nv_bfloat162 h) {
    return *(u32*)&h;
}
// split float4 -> bf16 hi/lo pairs, store 8B each to smem
__device__ __forceinline__ void cvt_store(char* smc, int off_hi, int off_lo, float4 v) {
    __nv_bfloat162 h0 = __floats2bfloat162_rn(v.x, v.y);
    __nv_bfloat162 h1 = __floats2bfloat162_rn(v.z, v.w);
    float2 f0 = __bfloat1622float2(h0);
    float2 f1 = __bfloat1622float2(h1);
    __nv_bfloat162 l0 = __floats2bfloat162_rn(v.x - f0.x, v.y - f0.y);
    __nv_bfloat162 l1 = __floats2bfloat162_rn(v.z - f1.x, v.w - f1.y);
    *(__nv_bfloat162*)(smc + off_hi)     = h0;
    *(__nv_bfloat162*)(smc + off_hi + 4) = h1;
    *(__nv_bfloat162*)(smc + off_lo)     = l0;
    *(__nv_bfloat162*)(smc + off_lo + 4) = l1;
}

__global__ void __launch_bounds__(NTH)
rbf_attn_mma(const float* __restrict__ Qg, const float* __restrict__ Kg,
             const float* __restrict__ Vg, float* __restrict__ Og)
{
    extern __shared__ char smc[];
    const u32 sb  = smem_u32(smc);
    const int tid = threadIdx.x;
    const int w   = tid >> 5;
    const int t   = tid & 31;
    const int bh  = blockIdx.y;
    const int qt  = (gridDim.x - 1) - blockIdx.x;    // heavy tiles first
    const int m0  = qt * BM;

    const float* Qh = Qg + (size_t)bh * N_ * D_;
    const float* Kh = Kg + (size_t)bh * N_ * D_;
    const float* Vh = Vg + (size_t)bh * N_ * D_;
    float*       Oh = Og + (size_t)bh * N_ * D_;

    // ---- stage Q (hi/lo bf16) into KH/KL region, compute qsq ----
    {
        const float4* Q4 = (const float4*)(Qh + (size_t)m0 * D_);
#pragma unroll
        for (int i = 0; i < 8; i++) {
            int fidx = i * NTH + tid;          // 0..1023
            int row  = fidx >> 4;
            int c4   = (fidx & 15) << 2;
            cvt_store(smc, OFF_KH + (row * LDH + c4) * 2,
                           OFF_KL + (row * LDH + c4) * 2, Q4[fidx]);
        }
        if (tid < BM) {
            float s = 0.f;
            const float4* Qr = (const float4*)(Qh + (size_t)(m0 + tid) * D_);
#pragma unroll
            for (int j = 0; j < 16; j++) {
                float4 v = Qr[j];
                s = fmaf(v.x, v.x, fmaf(v.y, v.y, fmaf(v.z, v.z, fmaf(v.w, v.w, s))));
            }
            ((float*)(smc + OFF_QSQ))[tid] = s;
        }
    }
    __syncthreads();

    // ---- extract Q A-fragments (persist in regs across all tiles) ----
    u32 qa[4][4], ql[4][4];
    {
        const int row = w * 16 + (((t >> 3) & 1) << 3) + (t & 7);
        const int cg  = (t >> 4) << 3;         // 0 or 8
#pragma unroll
        for (int kc = 0; kc < 4; kc++) {
            u32 addr = sb + OFF_KH + (u32)((row * LDH + 16 * kc + cg) * 2);
            ldsm4(addr, qa[kc]);
            ldsm4(addr + (OFF_KL - OFF_KH), ql[kc]);
        }
    }
    const float q0 = ((float*)(smc + OFF_QSQ))[w * 16 + (t >> 2)];
    const float q1 = ((float*)(smc + OFF_QSQ))[w * 16 + (t >> 2) + 8];
    const int m_r0 = m0 + w * 16 + (t >> 2);
    const int m_r1 = m_r0 + 8;

    float o[8][4];
#pragma unroll
    for (int i = 0; i < 8; i++)
#pragma unroll
        for (int j = 0; j < 4; j++) o[i][j] = 0.f;
    float l0 = 0.f, l1 = 0.f;

    const int nkt = qt + 1;
    for (int kt = 0; kt < nkt; kt++) {
        const int n0 = kt * BN;
        __syncthreads();    // previous-tile smem consumers done (also covers Q staging)

        // ---- load K,V (hi/lo bf16) + ksq ----
        {
            const float4* K4 = (const float4*)(Kh + (size_t)n0 * D_);
            const float4* V4 = (const float4*)(Vh + (size_t)n0 * D_);
#pragma unroll
            for (int i = 0; i < 8; i++) {
                int fidx = i * NTH + tid;
                int row  = fidx >> 4;
                int c4   = (fidx & 15) << 2;
                int off  = (row * LDH + c4) * 2;
                cvt_store(smc, OFF_KH + off, OFF_KL + off, K4[fidx]);
                cvt_store(smc, OFF_VH + off, OFF_VL + off, V4[fidx]);
            }
            if (tid < BN) {
                float s = 0.f;
                const float4* Kr = (const float4*)(Kh + (size_t)(n0 + tid) * D_);
#pragma unroll
                for (int j = 0; j < 16; j++) {
                    float4 v = Kr[j];
                    s = fmaf(v.x, v.x, fmaf(v.y, v.y, fmaf(v.z, v.z, fmaf(v.w, v.w, s))));
                }
                ((float*)(smc + OFF_KSQ))[tid] = s;
            }
        }
        __syncthreads();

        // ---- S = Q.K^T (3 compensated passes) ----
        float s[8][4];
#pragma unroll
        for (int i = 0; i < 8; i++)
#pragma unroll
            for (int j = 0; j < 4; j++) s[i][j] = 0.f;

#pragma unroll
        for (int nb = 0; nb < 8; nb++) {
#pragma unroll
            for (int g = 0; g < 2; g++) {
                u32 addr = sb + OFF_KH +
                    (u32)(((8 * nb + (t & 7)) * LDH + 32 * g + ((t >> 3) << 3)) * 2);
                u32 kb[4], kl[4];
                ldsm4(addr, kb);
                ldsm4(addr + (OFF_KL - OFF_KH), kl);
                mma16816(s[nb], qa[2*g],   kb[0], kb[1]);
                mma16816(s[nb], qa[2*g+1], kb[2], kb[3]);
                mma16816(s[nb], qa[2*g],   kl[0], kl[1]);
                mma16816(s[nb], qa[2*g+1], kl[2], kl[3]);
                mma16816(s[nb], ql[2*g],   kb[0], kb[1]);
                mma16816(s[nb], ql[2*g+1], kb[2], kb[3]);
            }
        }

        // ---- softmax: s -> p (in place), accumulate l ----
        const bool diag = (kt == qt);
        const float* ksq = (const float*)(smc + OFF_KSQ);
#pragma unroll
        for (int nb = 0; nb < 8; nb++) {
            float2 kk = *(const float2*)&ksq[8 * nb + 2 * (t & 3)];
            float c0 = -CEXP * (q0 + kk.x);
            float c1 = -CEXP * (q0 + kk.y);
            float c2 = -CEXP * (q1 + kk.x);
            float c3 = -CEXP * (q1 + kk.y);
            float p0 = ex2(fminf(fmaf(s[nb][0], 2.f * CEXP, c0), 0.f));
            float p1 = ex2(fminf(fmaf(s[nb][1], 2.f * CEXP, c1), 0.f));
            float p2 = ex2(fminf(fmaf(s[nb][2], 2.f * CEXP, c2), 0.f));
            float p3 = ex2(fminf(fmaf(s[nb][3], 2.f * CEXP, c3), 0.f));
            if (diag) {
                int nE = n0 + 8 * nb + 2 * (t & 3);
                if (nE     > m_r0) p0 = 0.f;
                if (nE + 1 > m_r0) p1 = 0.f;
                if (nE     > m_r1) p2 = 0.f;
                if (nE + 1 > m_r1) p3 = 0.f;
            }
            l0 += p0 + p1;
            l1 += p2 + p3;
            s[nb][0] = p0; s[nb][1] = p1; s[nb][2] = p2; s[nb][3] = p3;
        }

        // ---- O += P.V (3 compensated passes, P from registers) ----
#pragma unroll
        for (int g = 0; g < 2; g++) {
            u32 pha[2][4], pla[2][4];
#pragma unroll
            for (int c = 0; c < 2; c++) {
                const float* f0 = s[2 * (2*g + c)];
                const float* f1 = s[2 * (2*g + c) + 1];
                __nv_bfloat162 H0 = __floats2bfloat162_rn(f0[0], f0[1]);
                __nv_bfloat162 H1 = __floats2bfloat162_rn(f0[2], f0[3]);
                __nv_bfloat162 H2 = __floats2bfloat162_rn(f1[0], f1[1]);
                __nv_bfloat162 H3 = __floats2bfloat162_rn(f1[2], f1[3]);
                float2 g0 = __bfloat1622float2(H0);
                float2 g1 = __bfloat1622float2(H1);
                float2 g2 = __bfloat1622float2(H2);
                float2 g3 = __bfloat1622float2(H3);
                pha[c][0] = bits2(H0); pha[c][1] = bits2(H1);
                pha[c][2] = bits2(H2); pha[c][3] = bits2(H3);
                pla[c][0] = bits2(__floats2bfloat162_rn(f0[0]-g0.x, f0[1]-g0.y));
                pla[c][1] = bits2(__floats2bfloat162_rn(f0[2]-g1.x, f0[3]-g1.y));
                pla[c][2] = bits2(__floats2bfloat162_rn(f1[0]-g2.x, f1[1]-g2.y));
                pla[c][3] = bits2(__floats2bfloat162_rn(f1[2]-g3.x, f1[3]-g3.y));
            }
#pragma unroll
            for (int nd = 0; nd < 8; nd++) {
                u32 addr = sb + OFF_VH +
                    (u32)(((32 * g + ((t >> 3) << 3) + (t & 7)) * LDH + 8 * nd) * 2);
                u32 vh[4], vl[4];
                ldsm4t(addr, vh);
                ldsm4t(addr + (OFF_VL - OFF_VH), vl);
                mma16816(o[nd], pha[0], vh[0], vh[1]);
                mma16816(o[nd], pha[1], vh[2], vh[3]);
                mma16816(o[nd], pha[0], vl[0], vl[1]);
                mma16816(o[nd], pha[1], vl[2], vl[3]);
                mma16816(o[nd], pla[0], vh[0], vh[1]);
                mma16816(o[nd], pla[1], vh[2], vh[3]);
            }
        }
    }

    // ---- reduce l across the 4-lane quad sharing each row ----
    l0 += __shfl_xor_sync(0xffffffffu, l0, 1);
    l0 += __shfl_xor_sync(0xffffffffu, l0, 2);
    l1 += __shfl_xor_sync(0xffffffffu, l1, 1);
    l1 += __shfl_xor_sync(0xffffffffu, l1, 2);
    const float inv0 = 1.0f / l0;
    const float inv1 = 1.0f / l1;

    // ---- write O ----
#pragma unroll
    for (int nd = 0; nd < 8; nd++) {
        int dcol = 8 * nd + 2 * (t & 3);
        *(float2*)&Oh[(size_t)m_r0 * D_ + dcol] =
            make_float2(o[nd][0] * inv0, o[nd][1] * inv0);
        *(float2*)&Oh[(size_t)m_r1 * D_ + dcol] =
            make_float2(o[nd][2] * inv1, o[nd][3] * inv1);
    }
}

extern "C" void kernel_launch(void* const* d_in, const int* in_sizes, int n_in,
                              void* d_out, int out_size)
{
    const float* q = (const float*)d_in[0];
    const float* k = (const float*)d_in[1];
    const float* v = (const float*)d_in[2];
    float* o = (float*)d_out;
    (void)in_sizes; (void)n_in; (void)out_size;

    cudaFuncSetAttribute(rbf_attn_mma,
                         cudaFuncAttributeMaxDynamicSharedMemorySize, SMEM_BYTES);

    dim3 grid(N_ / BM, 32);
    rbf_attn_mma<<<grid, NTH, SMEM_BYTES>>>(q, k, v, o);
}

// round 6
// speedup vs baseline: 2.5038x; 1.1798x over previous
#include <cuda_runtime.h>
#include <cuda_bf16.h>
#include <cstdint>

// RBF-kernel causal attention via warp-level mma.sync (bf16, hi/lo compensated),
// with cp.async double-buffered staging of raw f32 K/V to hide LDG latency.
// B=2, H=16, N=2048, D=64. CTA: 64 queries, 4 warps, 64-key tiles.
// QK^T: 3 passes (qh*kh + qh*kl + ql*kh). PV: 3 passes (ph*vh + ph*vl + pl*vh).

#define N_   2048
#define D_   64
#define BM   64
#define BN   64
#define NTH  128
#define LDH  72                      // halves per bf16 smem row (144 B)
#define LDS_ 68                      // floats per f32 stage row (272 B)
#define CEXP 0.18033688011112042f    // log2(e)/8

// smem byte offsets
#define OFF_KH  0
#define OFF_KL  9216
#define OFF_VH  18432
#define OFF_VL  27648
#define OFF_KSQ 36864
#define OFF_QSQ 37120
#define STG_K   37376                // f32 stage: 64 rows x 68 floats
#define STG_V   (STG_K + 64*LDS_*4)  // 54784
#define SMEM_BYTES (STG_V + 64*LDS_*4)   // 72192

typedef uint32_t u32;

__device__ __forceinline__ u32 smem_u32(const void* p) {
    u32 a;
    asm("{ .reg .u64 t; cvta.to.shared.u64 t, %1; cvt.u32.u64 %0, t; }"
        : "=r"(a) : "l"(p));
    return a;
}
__device__ __forceinline__ float ex2(float x) {
    float y; asm("ex2.approx.f32 %0, %1;" : "=f"(y) : "f"(x)); return y;
}
__device__ __forceinline__ void cp16(u32 saddr, const void* g) {
    asm volatile("cp.async.cg.shared.global [%0], [%1], 16;"
                 :: "r"(saddr), "l"(g) : "memory");
}
__device__ __forceinline__ void cp_commit() {
    asm volatile("cp.async.commit_group;" ::: "memory");
}
__device__ __forceinline__ void cp_wait0() {
    asm volatile("cp.async.wait_group 0;" ::: "memory");
}
__device__ __forceinline__ void ldsm4(u32 addr, u32 r[4]) {
    asm volatile("ldmatrix.sync.aligned.m8n8.x4.shared.b16 {%0,%1,%2,%3}, [%4];"
                 : "=r"(r[0]), "=r"(r[1]), "=r"(r[2]), "=r"(r[3]) : "r"(addr));
}
__device__ __forceinline__ void ldsm4t(u32 addr, u32 r[4]) {
    asm volatile("ldmatrix.sync.aligned.m8n8.x4.trans.shared.b16 {%0,%1,%2,%3}, [%4];"
                 : "=r"(r[0]), "=r"(r[1]), "=r"(r[2]), "=r"(r[3]) : "r"(addr));
}
__device__ __forceinline__ void mma16816(float d[4], const u32 a[4], u32 b0, u32 b1) {
    asm volatile(
        "mma.sync.aligned.m16n8k16.row.col.f32.bf16.bf16.f32 "
        "{%0,%1,%2,%3}, {%4,%5,%6,%7}, {%8,%9}, {%0,%1,%2,%3};"
        : "+f"(d[0]), "+f"(d[1]), "+f"(d[2]), "+f"(d[3])
        : "r"(a[0]), "r"(a[1]), "r"(a[2]), "r"(a[3]), "r"(b0), "r"(b1));
}
__device__ __forceinline__ u32 bits2(__nv_bfloat162 h) { return *(u32*)&h; }

// split float4 -> bf16 hi/lo pairs, store 8B each to smem
__device__ __forceinline__ void cvt_store(char* smc, int off_hi, int off_lo, float4 v) {
    __nv_bfloat162 h0 = __floats2bfloat162_rn(v.x, v.y);
    __nv_bfloat162 h1 = __floats2bfloat162_rn(v.z, v.w);
    float2 f0 = __bfloat1622float2(h0);
    float2 f1 = __bfloat1622float2(h1);
    __nv_bfloat162 l0 = __floats2bfloat162_rn(v.x - f0.x, v.y - f0.y);
    __nv_bfloat162 l1 = __floats2bfloat162_rn(v.z - f1.x, v.w - f1.y);
    *(__nv_bfloat162*)(smc + off_hi)     = h0;
    *(__nv_bfloat162*)(smc + off_hi + 4) = h1;
    *(__nv_bfloat162*)(smc + off_lo)     = l0;
    *(__nv_bfloat162*)(smc + off_lo + 4) = l1;
}

__global__ void __launch_bounds__(NTH, 3)
rbf_attn_mma(const float* __restrict__ Qg, const float* __restrict__ Kg,
             const float* __restrict__ Vg, float* __restrict__ Og)
{
    extern __shared__ char smc[];
    const u32 sb  = smem_u32(smc);
    const int tid = threadIdx.x;
    const int w   = tid >> 5;
    const int t   = tid & 31;
    const int bh  = blockIdx.y;
    const int qt  = (gridDim.x - 1) - blockIdx.x;    // heavy tiles first
    const int m0  = qt * BM;
    const int nkt = qt + 1;

    const float* Qh = Qg + (size_t)bh * N_ * D_;
    const float* Kh = Kg + (size_t)bh * N_ * D_;
    const float* Vh = Vg + (size_t)bh * N_ * D_;
    float*       Oh = Og + (size_t)bh * N_ * D_;

    // per-thread stage addressing (fidx = i*NTH + tid)
    const int srow0 = tid >> 4;            // row advances by 8 per i
    const int sc4   = (tid & 15) << 2;
    const u32 stgk  = sb + STG_K + (u32)((srow0 * LDS_ + sc4) * 4);
    const u32 stgv  = sb + STG_V + (u32)((srow0 * LDS_ + sc4) * 4);

    // ---- issue cp.async for tile 0 ----
    {
        const char* Kp = (const char*)(Kh) + (size_t)tid * 16;
        const char* Vp = (const char*)(Vh) + (size_t)tid * 16;
#pragma unroll
        for (int i = 0; i < 8; i++) {
            cp16(stgk + (u32)(i * 8 * LDS_ * 4), Kp + (size_t)i * NTH * 16);
            cp16(stgv + (u32)(i * 8 * LDS_ * 4), Vp + (size_t)i * NTH * 16);
        }
        cp_commit();
    }

    // ---- stage Q (hi/lo bf16) into KH/KL region, compute qsq ----
    {
        const float4* Q4 = (const float4*)(Qh + (size_t)m0 * D_);
#pragma unroll
        for (int i = 0; i < 8; i++) {
            int fidx = i * NTH + tid;
            int row  = fidx >> 4;
            int c4   = (fidx & 15) << 2;
            cvt_store(smc, OFF_KH + (row * LDH + c4) * 2,
                           OFF_KL + (row * LDH + c4) * 2, Q4[fidx]);
        }
        if (tid < BM) {
            float s = 0.f;
            const float4* Qr = (const float4*)(Qh + (size_t)(m0 + tid) * D_);
#pragma unroll
            for (int j = 0; j < 16; j++) {
                float4 v = Qr[j];
                s = fmaf(v.x, v.x, fmaf(v.y, v.y, fmaf(v.z, v.z, fmaf(v.w, v.w, s))));
            }
            ((float*)(smc + OFF_QSQ))[tid] = s;
        }
    }
    __syncthreads();

    // ---- extract Q A-fragments (persist in regs across all tiles) ----
    u32 qa[4][4], ql[4][4];
    {
        const int row = w * 16 + (((t >> 3) & 1) << 3) + (t & 7);
        const int cg  = (t >> 4) << 3;
#pragma unroll
        for (int kc = 0; kc < 4; kc++) {
            u32 addr = sb + OFF_KH + (u32)((row * LDH + 16 * kc + cg) * 2);
            ldsm4(addr, qa[kc]);
            ldsm4(addr + (OFF_KL - OFF_KH), ql[kc]);
        }
    }
    const float q0 = ((float*)(smc + OFF_QSQ))[w * 16 + (t >> 2)];
    const float q1 = ((float*)(smc + OFF_QSQ))[w * 16 + (t >> 2) + 8];
    const int m_r0 = m0 + w * 16 + (t >> 2);
    const int m_r1 = m_r0 + 8;

    float o[8][4];
#pragma unroll
    for (int i = 0; i < 8; i++)
#pragma unroll
        for (int j = 0; j < 4; j++) o[i][j] = 0.f;
    float l0 = 0.f, l1 = 0.f;

    for (int kt = 0; kt < nkt; kt++) {
        const int n0 = kt * BN;

        // ---- wait for staged f32 K/V of this tile ----
        cp_wait0();
        __syncthreads();   // stage ready; previous tile's bf16 consumers done

        // ---- convert stage f32 -> bf16 hi/lo smem ----
        {
#pragma unroll
            for (int i = 0; i < 8; i++) {
                int fidx = i * NTH + tid;
                int row  = fidx >> 4;
                int c4   = (fidx & 15) << 2;
                float4 kv = *(const float4*)(smc + STG_K + (row * LDS_ + c4) * 4);
                float4 vv = *(const float4*)(smc + STG_V + (row * LDS_ + c4) * 4);
                int off = (row * LDH + c4) * 2;
                cvt_store(smc, OFF_KH + off, OFF_KL + off, kv);
                cvt_store(smc, OFF_VH + off, OFF_VL + off, vv);
            }
            if (tid < BN) {
                float s0 = 0.f, s1 = 0.f, s2 = 0.f, s3 = 0.f;
                const float* Kr = (const float*)(smc + STG_K) + tid * LDS_;
#pragma unroll
                for (int j = 0; j < 16; j += 4) {
                    float4 a = *(const float4*)(Kr + (j + 0) * 4);
                    float4 b = *(const float4*)(Kr + (j + 1) * 4);
                    float4 c = *(const float4*)(Kr + (j + 2) * 4);
                    float4 d = *(const float4*)(Kr + (j + 3) * 4);
                    s0 = fmaf(a.x, a.x, fmaf(a.y, a.y, fmaf(a.z, a.z, fmaf(a.w, a.w, s0))));
                    s1 = fmaf(b.x, b.x, fmaf(b.y, b.y, fmaf(b.z, b.z, fmaf(b.w, b.w, s1))));
                    s2 = fmaf(c.x, c.x, fmaf(c.y, c.y, fmaf(c.z, c.z, fmaf(c.w, c.w, s2))));
                    s3 = fmaf(d.x, d.x, fmaf(d.y, d.y, fmaf(d.z, d.z, fmaf(d.w, d.w, s3))));
                }
                ((float*)(smc + OFF_KSQ))[tid] = (s0 + s1) + (s2 + s3);
            }
        }
        __syncthreads();   // bf16 bufs + ksq ready; stage free for reuse

        // ---- issue cp.async for next tile (overlaps with MMA below) ----
        if (kt + 1 < nkt) {
            const char* Kp = (const char*)(Kh + (size_t)(n0 + BN) * D_) + (size_t)tid * 16;
            const char* Vp = (const char*)(Vh + (size_t)(n0 + BN) * D_) + (size_t)tid * 16;
#pragma unroll
            for (int i = 0; i < 8; i++) {
                cp16(stgk + (u32)(i * 8 * LDS_ * 4), Kp + (size_t)i * NTH * 16);
                cp16(stgv + (u32)(i * 8 * LDS_ * 4), Vp + (size_t)i * NTH * 16);
            }
        }
        cp_commit();       // commit (possibly empty) group so wait_group 0 is safe

        // ---- S = Q.K^T (3 compensated passes) ----
        float s[8][4];
#pragma unroll
        for (int i = 0; i < 8; i++)
#pragma unroll
            for (int j = 0; j < 4; j++) s[i][j] = 0.f;

#pragma unroll
        for (int nb = 0; nb < 8; nb++) {
#pragma unroll
            for (int g = 0; g < 2; g++) {
                u32 addr = sb + OFF_KH +
                    (u32)(((8 * nb + (t & 7)) * LDH + 32 * g + ((t >> 3) << 3)) * 2);
                u32 kb[4], kl[4];
                ldsm4(addr, kb);
                ldsm4(addr + (OFF_KL - OFF_KH), kl);
                mma16816(s[nb], qa[2*g],   kb[0], kb[1]);
                mma16816(s[nb], qa[2*g+1], kb[2], kb[3]);
                mma16816(s[nb], qa[2*g],   kl[0], kl[1]);
                mma16816(s[nb], qa[2*g+1], kl[2], kl[3]);
                mma16816(s[nb], ql[2*g],   kb[0], kb[1]);
                mma16816(s[nb], ql[2*g+1], kb[2], kb[3]);
            }
        }

        // ---- softmax: s -> p (in place), accumulate l ----
        const bool diag = (kt == qt);
        const float* ksq = (const float*)(smc + OFF_KSQ);
#pragma unroll
        for (int nb = 0; nb < 8; nb++) {
            float2 kk = *(const float2*)&ksq[8 * nb + 2 * (t & 3)];
            float c0 = -CEXP * (q0 + kk.x);
            float c1 = -CEXP * (q0 + kk.y);
            float c2 = -CEXP * (q1 + kk.x);
            float c3 = -CEXP * (q1 + kk.y);
            float p0 = ex2(fminf(fmaf(s[nb][0], 2.f * CEXP, c0), 0.f));
            float p1 = ex2(fminf(fmaf(s[nb][1], 2.f * CEXP, c1), 0.f));
            float p2 = ex2(fminf(fmaf(s[nb][2], 2.f * CEXP, c2), 0.f));
            float p3 = ex2(fminf(fmaf(s[nb][3], 2.f * CEXP, c3), 0.f));
            if (diag) {
                int nE = n0 + 8 * nb + 2 * (t & 3);
                if (nE     > m_r0) p0 = 0.f;
                if (nE + 1 > m_r0) p1 = 0.f;
                if (nE     > m_r1) p2 = 0.f;
                if (nE + 1 > m_r1) p3 = 0.f;
            }
            l0 += p0 + p1;
            l1 += p2 + p3;
            s[nb][0] = p0; s[nb][1] = p1; s[nb][2] = p2; s[nb][3] = p3;
        }

        // ---- O += P.V (3 compensated passes, P from registers) ----
#pragma unroll
        for (int g = 0; g < 2; g++) {
            u32 pha[2][4], pla[2][4];
#pragma unroll
            for (int c = 0; c < 2; c++) {
                const float* f0 = s[2 * (2*g + c)];
                const float* f1 = s[2 * (2*g + c) + 1];
                __nv_bfloat162 H0 = __floats2bfloat162_rn(f0[0], f0[1]);
                __nv_bfloat162 H1 = __floats2bfloat162_rn(f0[2], f0[3]);
                __nv_bfloat162 H2 = __floats2bfloat162_rn(f1[0], f1[1]);
                __nv_bfloat162 H3 = __floats2bfloat162_rn(f1[2], f1[3]);
                float2 g0 = __bfloat1622float2(H0);
                float2 g1 = __bfloat1622float2(H1);
                float2 g2 = __bfloat1622float2(H2);
                float2 g3 = __bfloat1622float2(H3);
                pha[c][0] = bits2(H0); pha[c][1] = bits2(H1);
                pha[c][2] = bits2(H2); pha[c][3] = bits2(H3);
                pla[c][0] = bits2(__floats2bfloat162_rn(f0[0]-g0.x, f0[1]-g0.y));
                pla[c][1] = bits2(__floats2bfloat162_rn(f0[2]-g1.x, f0[3]-g1.y));
                pla[c][2] = bits2(__floats2bfloat162_rn(f1[0]-g2.x, f1[1]-g2.y));
                pla[c][3] = bits2(__floats2bfloat162_rn(f1[2]-g3.x, f1[3]-g3.y));
            }
#pragma unroll
            for (int nd = 0; nd < 8; nd++) {
                u32 addr = sb + OFF_VH +
                    (u32)(((32 * g + ((t >> 3) << 3) + (t & 7)) * LDH + 8 * nd) * 2);
                u32 vh[4], vl[4];
                ldsm4t(addr, vh);
                ldsm4t(addr + (OFF_VL - OFF_VH), vl);
                mma16816(o[nd], pha[0], vh[0], vh[1]);
                mma16816(o[nd], pha[1], vh[2], vh[3]);
                mma16816(o[nd], pha[0], vl[0], vl[1]);
                mma16816(o[nd], pha[1], vl[2], vl[3]);
                mma16816(o[nd], pla[0], vh[0], vh[1]);
                mma16816(o[nd], pla[1], vh[2], vh[3]);
            }
        }
    }

    // ---- reduce l across the 4-lane quad sharing each row ----
    l0 += __shfl_xor_sync(0xffffffffu, l0, 1);
    l0 += __shfl_xor_sync(0xffffffffu, l0, 2);
    l1 += __shfl_xor_sync(0xffffffffu, l1, 1);
    l1 += __shfl_xor_sync(0xffffffffu, l1, 2);
    const float inv0 = 1.0f / l0;
    const float inv1 = 1.0f / l1;

    // ---- write O ----
#pragma unroll
    for (int nd = 0; nd < 8; nd++) {
        int dcol = 8 * nd + 2 * (t & 3);
        *(float2*)&Oh[(size_t)m_r0 * D_ + dcol] =
            make_float2(o[nd][0] * inv0, o[nd][1] * inv0);
        *(float2*)&Oh[(size_t)m_r1 * D_ + dcol] =
            make_float2(o[nd][2] * inv1, o[nd][3] * inv1);
    }
}

extern "C" void kernel_launch(void* const* d_in, const int* in_sizes, int n_in,
                              void* d_out, int out_size)
{
    const float* q = (const float*)d_in[0];
    const float* k = (const float*)d_in[1];
    const float* v = (const float*)d_in[2];
    float* o = (float*)d_out;
    (void)in_sizes; (void)n_in; (void)out_size;

    cudaFuncSetAttribute(rbf_attn_mma,
                         cudaFuncAttributeMaxDynamicSharedMemorySize, SMEM_BYTES);

    dim3 grid(N_ / BM, 32);
    rbf_attn_mma<<<grid, NTH, SMEM_BYTES>>>(q, k, v, o);
}

// round 7
// speedup vs baseline: 2.9121x; 1.1631x over previous
#include <cuda_runtime.h>
#include <cuda_bf16.h>
#include <cstdint>

// RBF-kernel causal attention via warp-level mma.sync (bf16, hi/lo compensated).
// Round 6: prep kernel precomputes global bf16 hi/lo K/V + per-key ||k||^2;
// main kernel cp.asyncs ready bf16 tiles into a 2-stage double buffer.
// B=2, H=16, N=2048, D=64. CTA: 64 queries, 4 warps, 64-key tiles.

#define N_   2048
#define D_   64
#define BM   64
#define BN   64
#define NTH  128
#define LDH  72                      // halves per bf16 smem row (144 B)
#define CEXP 0.18033688011112042f    // log2(e)/8

#define MAT    9216                  // 64 rows * 144 B
#define B_KH   0
#define B_KL   MAT
#define B_VH   (2*MAT)
#define B_VL   (3*MAT)
#define B_KSQ  (4*MAT)
#define BUF    (4*MAT + 256)         // 37120
#define OFF_QSQ (2*BUF)              // 74240
#define SMEM_BYTES (OFF_QSQ + 256)   // 74496

#define TOT4 (2*16*2048*16)          // float4 count per tensor

typedef uint32_t u32;

__device__ uint2 g_KH[TOT4];
__device__ uint2 g_KL[TOT4];
__device__ uint2 g_VH[TOT4];
__device__ uint2 g_VL[TOT4];
__device__ float g_ksq[2*16*2048];

__device__ __forceinline__ u32 smem_u32(const void* p) {
    u32 a;
    asm("{ .reg .u64 t; cvta.to.shared.u64 t, %1; cvt.u32.u64 %0, t; }"
        : "=r"(a) : "l"(p));
    return a;
}
__device__ __forceinline__ float ex2(float x) {
    float y; asm("ex2.approx.f32 %0, %1;" : "=f"(y) : "f"(x)); return y;
}
__device__ __forceinline__ void cp16(u32 saddr, const void* g) {
    asm volatile("cp.async.cg.shared.global [%0], [%1], 16;"
                 :: "r"(saddr), "l"(g) : "memory");
}
__device__ __forceinline__ void cp_commit() {
    asm volatile("cp.async.commit_group;" ::: "memory");
}
__device__ __forceinline__ void cp_wait0() {
    asm volatile("cp.async.wait_group 0;" ::: "memory");
}
__device__ __forceinline__ void ldsm4(u32 addr, u32 r[4]) {
    asm volatile("ldmatrix.sync.aligned.m8n8.x4.shared.b16 {%0,%1,%2,%3}, [%4];"
                 : "=r"(r[0]), "=r"(r[1]), "=r"(r[2]), "=r"(r[3]) : "r"(addr));
}
__device__ __forceinline__ void ldsm4t(u32 addr, u32 r[4]) {
    asm volatile("ldmatrix.sync.aligned.m8n8.x4.trans.shared.b16 {%0,%1,%2,%3}, [%4];"
                 : "=r"(r[0]), "=r"(r[1]), "=r"(r[2]), "=r"(r[3]) : "r"(addr));
}
__device__ __forceinline__ void mma16816(float d[4], const u32 a[4], u32 b0, u32 b1) {
    asm volatile(
        "mma.sync.aligned.m16n8k16.row.col.f32.bf16.bf16.f32 "
        "{%0,%1,%2,%3}, {%4,%5,%6,%7}, {%8,%9}, {%0,%1,%2,%3};"
        : "+f"(d[0]), "+f"(d[1]), "+f"(d[2]), "+f"(d[3])
        : "r"(a[0]), "r"(a[1]), "r"(a[2]), "r"(a[3]), "r"(b0), "r"(b1));
}
__device__ __forceinline__ u32 bits2(__nv_bfloat162 h) { return *(u32*)&h; }

__device__ __forceinline__ void split4(float4 v, uint2& hi, uint2& lo) {
    __nv_bfloat162 h0 = __floats2bfloat162_rn(v.x, v.y);
    __nv_bfloat162 h1 = __floats2bfloat162_rn(v.z, v.w);
    float2 f0 = __bfloat1622float2(h0);
    float2 f1 = __bfloat1622float2(h1);
    __nv_bfloat162 l0 = __floats2bfloat162_rn(v.x - f0.x, v.y - f0.y);
    __nv_bfloat162 l1 = __floats2bfloat162_rn(v.z - f1.x, v.w - f1.y);
    hi = make_uint2(bits2(h0), bits2(h1));
    lo = make_uint2(bits2(l0), bits2(l1));
}
// split float4 -> bf16 hi/lo pairs, store 8B each to smem (Q staging)
__device__ __forceinline__ void cvt_store(char* smc, int off_hi, int off_lo, float4 v) {
    uint2 hi, lo;
    split4(v, hi, lo);
    *(uint2*)(smc + off_hi) = hi;
    *(uint2*)(smc + off_lo) = lo;
}

// ---------------- prep: f32 K/V -> bf16 hi/lo globals + ksq ----------------
__global__ void __launch_bounds__(256)
prep_kernel(const float* __restrict__ K, const float* __restrict__ V)
{
    const int i = blockIdx.x * 256 + threadIdx.x;     // float4 index
    float4 k = ((const float4*)K)[i];
    float4 v = ((const float4*)V)[i];
    uint2 hi, lo;
    split4(k, hi, lo);
    g_KH[i] = hi; g_KL[i] = lo;
    split4(v, hi, lo);
    g_VH[i] = hi; g_VL[i] = lo;

    float s = fmaf(k.x, k.x, fmaf(k.y, k.y, fmaf(k.z, k.z, k.w * k.w)));
    s += __shfl_xor_sync(0xffffffffu, s, 1, 16);
    s += __shfl_xor_sync(0xffffffffu, s, 2, 16);
    s += __shfl_xor_sync(0xffffffffu, s, 4, 16);
    s += __shfl_xor_sync(0xffffffffu, s, 8, 16);
    if ((threadIdx.x & 15) == 0) g_ksq[i >> 4] = s;
}

// cp.async one full key-tile (KH,KL,VH,VL + ksq) into smem buffer at dst
__device__ __forceinline__ void cp_tile(u32 dst, size_t rowbase, int tid)
{
    const char* khg = (const char*)g_KH + rowbase * 128;
    const char* klg = (const char*)g_KL + rowbase * 128;
    const char* vhg = (const char*)g_VH + rowbase * 128;
    const char* vlg = (const char*)g_VL + rowbase * 128;
#pragma unroll
    for (int i = 0; i < 4; i++) {
        int c   = i * 128 + tid;        // 0..511
        int row = c >> 3;
        int c8  = c & 7;
        u32 so  = (u32)(row * 144 + c8 * 16);
        size_t go = (size_t)row * 128 + (size_t)c8 * 16;
        cp16(dst + B_KH + so, khg + go);
        cp16(dst + B_KL + so, klg + go);
        cp16(dst + B_VH + so, vhg + go);
        cp16(dst + B_VL + so, vlg + go);
    }
    if (tid < 16)
        cp16(dst + B_KSQ + (u32)(tid * 16), (const char*)(g_ksq + rowbase) + tid * 16);
}

// ---------------- main kernel ----------------
__global__ void __launch_bounds__(NTH, 3)
rbf_attn_mma(const float* __restrict__ Qg, float* __restrict__ Og)
{
    extern __shared__ char smc[];
    const u32 sb  = smem_u32(smc);
    const int tid = threadIdx.x;
    const int w   = tid >> 5;
    const int t   = tid & 31;
    const int bh  = blockIdx.y;
    const int qt  = (gridDim.x - 1) - blockIdx.x;    // heavy tiles first
    const int m0  = qt * BM;
    const int nkt = qt + 1;

    const float* Qh = Qg + (size_t)bh * N_ * D_;
    float*       Oh = Og + (size_t)bh * N_ * D_;

    // ---- prologue: cp tile 0 into buffer 0 ----
    cp_tile(sb, (size_t)bh * N_, tid);
    cp_commit();

    // ---- stage Q (hi/lo bf16) into buffer 1's KH/KL region, compute qsq ----
    {
        const float4* Q4 = (const float4*)(Qh + (size_t)m0 * D_);
#pragma unroll
        for (int i = 0; i < 8; i++) {
            int fidx = i * NTH + tid;
            int row  = fidx >> 4;
            int c4   = (fidx & 15) << 2;
            cvt_store(smc, BUF + B_KH + (row * LDH + c4) * 2,
                           BUF + B_KL + (row * LDH + c4) * 2, Q4[fidx]);
        }
        if (tid < BM) {
            float s = 0.f;
            const float4* Qr = (const float4*)(Qh + (size_t)(m0 + tid) * D_);
#pragma unroll
            for (int j = 0; j < 16; j++) {
                float4 v = Qr[j];
                s = fmaf(v.x, v.x, fmaf(v.y, v.y, fmaf(v.z, v.z, fmaf(v.w, v.w, s))));
            }
            ((float*)(smc + OFF_QSQ))[tid] = s;
        }
    }
    __syncthreads();

    // ---- extract Q A-fragments (persist in regs across all tiles) ----
    u32 qa[4][4], ql[4][4];
    {
        const int row = w * 16 + (((t >> 3) & 1) << 3) + (t & 7);
        const int cg  = (t >> 4) << 3;
#pragma unroll
        for (int kc = 0; kc < 4; kc++) {
            u32 addr = sb + BUF + B_KH + (u32)((row * LDH + 16 * kc + cg) * 2);
            ldsm4(addr, qa[kc]);
            ldsm4(addr + MAT, ql[kc]);
        }
    }
    const float q0 = ((float*)(smc + OFF_QSQ))[w * 16 + (t >> 2)];
    const float q1 = ((float*)(smc + OFF_QSQ))[w * 16 + (t >> 2) + 8];
    const int m_r0 = m0 + w * 16 + (t >> 2);
    const int m_r1 = m_r0 + 8;

    float o[8][4];
#pragma unroll
    for (int i = 0; i < 8; i++)
#pragma unroll
        for (int j = 0; j < 4; j++) o[i][j] = 0.f;
    float l0 = 0.f, l1 = 0.f;

    for (int kt = 0; kt < nkt; kt++) {
        const int n0 = kt * BN;
        const u32 cb = sb + (u32)((kt & 1) * BUF);
        const char* cc = smc + (size_t)((kt & 1) * BUF);

        // ---- wait for this tile's cp group; one sync per tile ----
        cp_wait0();
        __syncthreads();

        // ---- issue cp.async for tile kt+1 into the other buffer ----
        if (kt + 1 < nkt)
            cp_tile(sb + (u32)(((kt + 1) & 1) * BUF),
                    (size_t)bh * N_ + (size_t)(n0 + BN), tid);
        cp_commit();

        // ---- S = Q.K^T (3 compensated passes) ----
        float s[8][4];
#pragma unroll
        for (int i = 0; i < 8; i++)
#pragma unroll
            for (int j = 0; j < 4; j++) s[i][j] = 0.f;

#pragma unroll
        for (int nb = 0; nb < 8; nb++) {
#pragma unroll
            for (int g = 0; g < 2; g++) {
                u32 addr = cb + B_KH +
                    (u32)(((8 * nb + (t & 7)) * LDH + 32 * g + ((t >> 3) << 3)) * 2);
                u32 kb[4], kl[4];
                ldsm4(addr, kb);
                ldsm4(addr + MAT, kl);
                mma16816(s[nb], qa[2*g],   kb[0], kb[1]);
                mma16816(s[nb], qa[2*g+1], kb[2], kb[3]);
                mma16816(s[nb], qa[2*g],   kl[0], kl[1]);
                mma16816(s[nb], qa[2*g+1], kl[2], kl[3]);
                mma16816(s[nb], ql[2*g],   kb[0], kb[1]);
                mma16816(s[nb], ql[2*g+1], kb[2], kb[3]);
            }
        }

        // ---- softmax: s -> p (in place), accumulate l ----
        const bool diag = (kt == qt);
        const float* ksq = (const float*)(cc + B_KSQ);
#pragma unroll
        for (int nb = 0; nb < 8; nb++) {
            float2 kk = *(const float2*)&ksq[8 * nb + 2 * (t & 3)];
            float c0 = -CEXP * (q0 + kk.x);
            float c1 = -CEXP * (q0 + kk.y);
            float c2 = -CEXP * (q1 + kk.x);
            float c3 = -CEXP * (q1 + kk.y);
            float p0 = ex2(fminf(fmaf(s[nb][0], 2.f * CEXP, c0), 0.f));
            float p1 = ex2(fminf(fmaf(s[nb][1], 2.f * CEXP, c1), 0.f));
            float p2 = ex2(fminf(fmaf(s[nb][2], 2.f * CEXP, c2), 0.f));
            float p3 = ex2(fminf(fmaf(s[nb][3], 2.f * CEXP, c3), 0.f));
            if (diag) {
                int nE = n0 + 8 * nb + 2 * (t & 3);
                if (nE     > m_r0) p0 = 0.f;
                if (nE + 1 > m_r0) p1 = 0.f;
                if (nE     > m_r1) p2 = 0.f;
                if (nE + 1 > m_r1) p3 = 0.f;
            }
            l0 += p0 + p1;
            l1 += p2 + p3;
            s[nb][0] = p0; s[nb][1] = p1; s[nb][2] = p2; s[nb][3] = p3;
        }

        // ---- O += P.V (3 compensated passes, P from registers) ----
#pragma unroll
        for (int g = 0; g < 2; g++) {
            u32 pha[2][4], pla[2][4];
#pragma unroll
            for (int c = 0; c < 2; c++) {
                const float* f0 = s[2 * (2*g + c)];
                const float* f1 = s[2 * (2*g + c) + 1];
                __nv_bfloat162 H0 = __floats2bfloat162_rn(f0[0], f0[1]);
                __nv_bfloat162 H1 = __floats2bfloat162_rn(f0[2], f0[3]);
                __nv_bfloat162 H2 = __floats2bfloat162_rn(f1[0], f1[1]);
                __nv_bfloat162 H3 = __floats2bfloat162_rn(f1[2], f1[3]);
                float2 g0 = __bfloat1622float2(H0);
                float2 g1 = __bfloat1622float2(H1);
                float2 g2 = __bfloat1622float2(H2);
                float2 g3 = __bfloat1622float2(H3);
                pha[c][0] = bits2(H0); pha[c][1] = bits2(H1);
                pha[c][2] = bits2(H2); pha[c][3] = bits2(H3);
                pla[c][0] = bits2(__floats2bfloat162_rn(f0[0]-g0.x, f0[1]-g0.y));
                pla[c][1] = bits2(__floats2bfloat162_rn(f0[2]-g1.x, f0[3]-g1.y));
                pla[c][2] = bits2(__floats2bfloat162_rn(f1[0]-g2.x, f1[1]-g2.y));
                pla[c][3] = bits2(__floats2bfloat162_rn(f1[2]-g3.x, f1[3]-g3.y));
            }
#pragma unroll
            for (int nd = 0; nd < 8; nd++) {
                u32 addr = cb + B_VH +
                    (u32)(((32 * g + ((t >> 3) << 3) + (t & 7)) * LDH + 8 * nd) * 2);
                u32 vh[4], vl[4];
                ldsm4t(addr, vh);
                ldsm4t(addr + MAT, vl);
                mma16816(o[nd], pha[0], vh[0], vh[1]);
                mma16816(o[nd], pha[1], vh[2], vh[3]);
                mma16816(o[nd], pha[0], vl[0], vl[1]);
                mma16816(o[nd], pha[1], vl[2], vl[3]);
                mma16816(o[nd], pla[0], vh[0], vh[1]);
                mma16816(o[nd], pla[1], vh[2], vh[3]);
            }
        }
    }

    // ---- reduce l across the 4-lane quad sharing each row ----
    l0 += __shfl_xor_sync(0xffffffffu, l0, 1);
    l0 += __shfl_xor_sync(0xffffffffu, l0, 2);
    l1 += __shfl_xor_sync(0xffffffffu, l1, 1);
    l1 += __shfl_xor_sync(0xffffffffu, l1, 2);
    const float inv0 = 1.0f / l0;
    const float inv1 = 1.0f / l1;

    // ---- write O ----
#pragma unroll
    for (int nd = 0; nd < 8; nd++) {
        int dcol = 8 * nd + 2 * (t & 3);
        *(float2*)&Oh[(size_t)m_r0 * D_ + dcol] =
            make_float2(o[nd][0] * inv0, o[nd][1] * inv0);
        *(float2*)&Oh[(size_t)m_r1 * D_ + dcol] =
            make_float2(o[nd][2] * inv1, o[nd][3] * inv1);
    }
}

extern "C" void kernel_launch(void* const* d_in, const int* in_sizes, int n_in,
                              void* d_out, int out_size)
{
    const float* q = (const float*)d_in[0];
    const float* k = (const float*)d_in[1];
    const float* v = (const float*)d_in[2];
    float* o = (float*)d_out;
    (void)in_sizes; (void)n_in; (void)out_size;

    prep_kernel<<<TOT4 / 256, 256>>>(k, v);

    cudaFuncSetAttribute(rbf_attn_mma,
                         cudaFuncAttributeMaxDynamicSharedMemorySize, SMEM_BYTES);

    dim3 grid(N_ / BM, 32);
    rbf_attn_mma<<<grid, NTH, SMEM_BYTES>>>(q, o);
}